// round 15
// baseline (speedup 1.0000x reference)
#include <cuda_runtime.h>
#include <cuda_bf16.h>
#include <cstdint>
#include <math.h>

// Problem constants
constexpr int BB  = 2;
constexpr int LL  = 2048;
constexpr int DD  = 1024;
constexpr int TD  = 3072;   // 3*D
constexpr int HH  = 16;     // heads
constexpr int HD  = 64;     // head dim
constexpr int CC  = 128;    // chunk size
constexpr int NCH = 16;     // num chunks
constexpr float INV_SCALE = 1.0f / 32.0f;   // 1/sqrt(1024)
constexpr int ML  = BB * LL;                // 4096 rows

// ---------------- device scratch (static globals: allocation-free) ----------
__device__ float g_qkv  [(size_t)BB * LL * TD];
__device__ float g_qpool[BB * NCH * DD];
__device__ float g_kpool[BB * NCH * DD];
__device__ float g_csum [BB * NCH * DD];
__device__ float g_M    [(size_t)BB * HH * NCH * 7 * HD];  // moments M_p[d]
__device__ float g_Sp   [BB * HH * NCH * 7];               // scalar sums S_p

// split bf16 operands for tensor-core GEMMs
__device__ __nv_bfloat16 g_x_hi   [(size_t)ML * DD];
__device__ __nv_bfloat16 g_x_lo   [(size_t)ML * DD];
__device__ __nv_bfloat16 g_attn_hi[(size_t)ML * DD];
__device__ __nv_bfloat16 g_attn_lo[(size_t)ML * DD];
__device__ __nv_bfloat16 g_wqkv_hi[(size_t)TD * DD];   // transposed [N=3072][K=1024]
__device__ __nv_bfloat16 g_wqkv_lo[(size_t)TD * DD];
__device__ __nv_bfloat16 g_wo_hi  [(size_t)DD * DD];   // transposed [N=1024][K=1024]
__device__ __nv_bfloat16 g_wo_lo  [(size_t)DD * DD];

// ================= baseline-PTX helpers =====================================
__device__ __forceinline__ uint32_t smem_u32(const void* p) {
    uint32_t a;
    asm("{ .reg .u64 t; cvta.to.shared.u64 t, %1; cvt.u32.u64 %0, t; }"
        : "=r"(a) : "l"(p));
    return a;
}
__device__ __forceinline__ void cp_async16(uint32_t dst, const void* src) {
    asm volatile("cp.async.cg.shared.global [%0], [%1], 16;" :: "r"(dst), "l"(src));
}
__device__ __forceinline__ void cp_commit() {
    asm volatile("cp.async.commit_group;" ::: "memory");
}
template <int NW>
__device__ __forceinline__ void cp_wait() {
    asm volatile("cp.async.wait_group %0;" :: "n"(NW) : "memory");
}
__device__ __forceinline__ void ldm_x4(uint32_t* r, uint32_t addr) {
    asm volatile("ldmatrix.sync.aligned.m8n8.x4.shared.b16 {%0,%1,%2,%3}, [%4];"
                 : "=r"(r[0]), "=r"(r[1]), "=r"(r[2]), "=r"(r[3]) : "r"(addr));
}
__device__ __forceinline__ void mma16816(float* d, const uint32_t* a, const uint32_t* b) {
    asm volatile(
        "mma.sync.aligned.m16n8k16.row.col.f32.bf16.bf16.f32 "
        "{%0,%1,%2,%3}, {%4,%5,%6,%7}, {%8,%9}, {%0,%1,%2,%3};"
        : "+f"(d[0]), "+f"(d[1]), "+f"(d[2]), "+f"(d[3])
        : "r"(a[0]), "r"(a[1]), "r"(a[2]), "r"(a[3]), "r"(b[0]), "r"(b[1]));
}

// ================= merged split/transpose conversion kernel =================
// blocks [0, NB_RM): row-major split of x -> g_x_hi/lo (256 elems/block... )
// blocks [NB_RM, NB_RM+NB_T1): transpose+split w_qkv
// blocks [.., +NB_T2): transpose+split w_o
constexpr int NB_RM = (ML * DD) / 256;
constexpr int NB_T1 = (TD / 32) * (DD / 32);
constexpr int NB_T2 = (DD / 32) * (DD / 32);

__global__ void split_all(const float* __restrict__ x,
                          const float* __restrict__ wqkv,
                          const float* __restrict__ wo)
{
    int blk = blockIdx.x;
    int t = threadIdx.x;
    if (blk < NB_RM) {
        int i = blk * 256 + t;
        float v = x[i];
        __nv_bfloat16 h = __float2bfloat16(v);
        g_x_hi[i] = h;
        g_x_lo[i] = __float2bfloat16(v - __bfloat162float(h));
        return;
    }
    blk -= NB_RM;
    const float* in;
    __nv_bfloat16 *hi, *lo;
    int Nc, bx;
    if (blk < NB_T1) {
        in = wqkv; hi = g_wqkv_hi; lo = g_wqkv_lo; Nc = TD;
        bx = blk % (TD / 32);
        blk /= (TD / 32);
    } else {
        blk -= NB_T1;
        in = wo; hi = g_wo_hi; lo = g_wo_lo; Nc = DD;
        bx = blk % (DD / 32);
        blk /= (DD / 32);
    }
    int nBase = bx * 32, kBase = blk * 32;

    __shared__ float tile[32][33];
    int tx = t & 31, ty = t >> 5;     // 32 x 8
#pragma unroll
    for (int j = 0; j < 32; j += 8)
        tile[ty + j][tx] = in[(size_t)(kBase + ty + j) * Nc + nBase + tx];
    __syncthreads();
#pragma unroll
    for (int j = 0; j < 32; j += 8) {
        float v = tile[tx][ty + j];
        size_t o = (size_t)(nBase + ty + j) * DD + kBase + tx;
        __nv_bfloat16 h = __float2bfloat16(v);
        hi[o] = h;
        lo[o] = __float2bfloat16(v - __bfloat162float(h));
    }
}

// ================= mma.sync GEMM — single-sync pipeline + pooling epilogue ==
constexpr int GP    = 40;
constexpr int GTILE = 128 * GP;
constexpr int GSTG  = 4 * GTILE;
constexpr int GSMEM = 2 * GSTG * 2;

template <int MODE>
__global__ __launch_bounds__(256, 2) void mma_gemm(const float* __restrict__ bias,
                                                   float* __restrict__ Cext)
{
    const int N = (MODE == 0) ? TD : DD;
    const int K = DD;
    const __nv_bfloat16* Ah = (MODE == 0) ? g_x_hi : g_attn_hi;
    const __nv_bfloat16* Al = (MODE == 0) ? g_x_lo : g_attn_lo;
    const __nv_bfloat16* Bh = (MODE == 0) ? g_wqkv_hi : g_wo_hi;
    const __nv_bfloat16* Bl = (MODE == 0) ? g_wqkv_lo : g_wo_lo;
    float* C = (MODE == 0) ? g_qkv : Cext;

    extern __shared__ __nv_bfloat16 smem[];
    uint32_t sb = smem_u32(smem);

    int t = threadIdx.x, lane = t & 31, wid = t >> 5;
    int wm = wid & 3, wn = wid >> 2;
    int bm = blockIdx.y * 128, bn = blockIdx.x * 128;

    const __nv_bfloat16* srcs[4] = {
        Ah + (size_t)bm * K, Al + (size_t)bm * K,
        Bh + (size_t)bn * K, Bl + (size_t)bn * K
    };

    int r0c = t >> 2, c0c = t & 3;
    int r1c = (t + 256) >> 2, c1c = (t + 256) & 3;

    auto load_stage = [&](int st, int s) {
        int ks = s * 32;
#pragma unroll
        for (int ten = 0; ten < 4; ten++) {
            const __nv_bfloat16* base = srcs[ten] + ks;
            uint32_t dst = sb + (uint32_t)(st * GSTG + ten * GTILE) * 2;
            cp_async16(dst + (uint32_t)(r0c * GP + c0c * 8) * 2,
                       base + (size_t)r0c * K + c0c * 8);
            cp_async16(dst + (uint32_t)(r1c * GP + c1c * 8) * 2,
                       base + (size_t)r1c * K + c1c * 8);
        }
    };

    float acc[2][8][4];
#pragma unroll
    for (int i = 0; i < 2; i++)
#pragma unroll
        for (int j = 0; j < 8; j++)
#pragma unroll
            for (int q = 0; q < 4; q++) acc[i][j][q] = 0.f;

    load_stage(0, 0);
    cp_commit();

    const int S = K / 32;
    for (int s = 0; s < S; s++) {
        // wait for load(s) (the only pending group), one barrier per stage,
        // then issue load(s+1) with the whole compute stage to land.
        cp_wait<0>();
        __syncthreads();
        if (s + 1 < S) { load_stage((s + 1) & 1, s + 1); cp_commit(); }

        int st = s & 1;
        uint32_t baseAh = sb + (uint32_t)(st * GSTG + 0 * GTILE) * 2;
        uint32_t baseAl = sb + (uint32_t)(st * GSTG + 1 * GTILE) * 2;
        uint32_t baseBh = sb + (uint32_t)(st * GSTG + 2 * GTILE) * 2;
        uint32_t baseBl = sb + (uint32_t)(st * GSTG + 3 * GTILE) * 2;

#pragma unroll
        for (int kk = 0; kk < 2; kk++) {
            int k0 = kk * 16;
            uint32_t ah[2][4], al[2][4], bb[4][4];

            uint32_t aoff = (uint32_t)(((wm * 32 + (lane & 15)) * GP
                                        + k0 + (lane >> 4) * 8) * 2);
            ldm_x4(ah[0], baseAh + aoff);
            ldm_x4(ah[1], baseAh + aoff + 16 * GP * 2);

            uint32_t brow = (uint32_t)(wn * 64 + (lane & 7) + ((lane >> 4) << 3));
            uint32_t boff = (uint32_t)((brow * GP + k0 + ((lane >> 3) & 1) * 8) * 2);
#pragma unroll
            for (int bt = 0; bt < 4; bt++)
                ldm_x4(bb[bt], baseBh + boff + bt * 16 * GP * 2);

            // pass 1: Ah * Bh
#pragma unroll
            for (int mt = 0; mt < 2; mt++)
#pragma unroll
                for (int nt = 0; nt < 8; nt++)
                    mma16816(acc[mt][nt], ah[mt], &bb[nt >> 1][(nt & 1) * 2]);

            // pass 2: Al * Bh
            ldm_x4(al[0], baseAl + aoff);
            ldm_x4(al[1], baseAl + aoff + 16 * GP * 2);
#pragma unroll
            for (int mt = 0; mt < 2; mt++)
#pragma unroll
                for (int nt = 0; nt < 8; nt++)
                    mma16816(acc[mt][nt], al[mt], &bb[nt >> 1][(nt & 1) * 2]);

            // pass 3: Ah * Bl
#pragma unroll
            for (int bt = 0; bt < 4; bt++)
                ldm_x4(bb[bt], baseBl + boff + bt * 16 * GP * 2);
#pragma unroll
            for (int mt = 0; mt < 2; mt++)
#pragma unroll
                for (int nt = 0; nt < 8; nt++)
                    mma16816(acc[mt][nt], ah[mt], &bb[nt >> 1][(nt & 1) * 2]);
        }
    }

    int mbase = bm + wm * 32, nbase = bn + wn * 64;
    int rr = lane >> 2, cc = (lane & 3) * 2;
#pragma unroll
    for (int mt = 0; mt < 2; mt++) {
#pragma unroll
        for (int nt = 0; nt < 8; nt++) {
            int col = nbase + nt * 8 + cc;
            float2 bv = *(const float2*)(bias + col);
            int row0 = mbase + mt * 16 + rr;
            float2 o0 = { acc[mt][nt][0] + bv.x, acc[mt][nt][1] + bv.y };
            float2 o1 = { acc[mt][nt][2] + bv.x, acc[mt][nt][3] + bv.y };
            *(float2*)(C + (size_t)row0 * N + col)       = o0;
            *(float2*)(C + (size_t)(row0 + 8) * N + col) = o1;
        }
    }

    // ---- fused chunk pooling (MODE 0): this CTA tile = chunk blockIdx.y ----
    if (MODE == 0) {
        float cs[16];
#pragma unroll
        for (int nt = 0; nt < 8; nt++) {
            cs[nt * 2 + 0] = acc[0][nt][0] + acc[0][nt][2]
                           + acc[1][nt][0] + acc[1][nt][2];
            cs[nt * 2 + 1] = acc[0][nt][1] + acc[0][nt][3]
                           + acc[1][nt][1] + acc[1][nt][3];
        }
#pragma unroll
        for (int off = 16; off >= 4; off >>= 1)
#pragma unroll
            for (int i = 0; i < 16; i++)
                cs[i] += __shfl_down_sync(0xffffffffu, cs[i], off);

        float* red = (float*)smem;
        __syncthreads();   // all warps done with pipeline smem before reuse
        if (lane < 4) {
#pragma unroll
            for (int nt = 0; nt < 8; nt++) {
                red[wm * 128 + wn * 64 + nt * 8 + lane * 2 + 0] = cs[nt * 2 + 0];
                red[wm * 128 + wn * 64 + nt * 8 + lane * 2 + 1] = cs[nt * 2 + 1];
            }
        }
        __syncthreads();
        if (t < 128) {
            float sum = red[0 * 128 + t] + red[1 * 128 + t]
                      + red[2 * 128 + t] + red[3 * 128 + t];
            int gcol = bn + t;
            sum += 128.0f * bias[gcol];
            int chunk = blockIdx.y;
            if (gcol < DD)
                g_qpool[chunk * DD + gcol] = sum * (1.0f / 128.0f);
            else if (gcol < 2 * DD)
                g_kpool[chunk * DD + (gcol - DD)] = sum * (1.0f / 128.0f);
            else
                g_csum[chunk * DD + (gcol - 2 * DD)] = sum;
        }
    }
}

// ---------------- fused c2t + moments: one block per (b,h,n), 256 thr -------
__global__ __launch_bounds__(256) void c2t_moments_kernel()   // grid = BB*HH*NCH
{
    __shared__ float c2s[128];
    __shared__ float Mpart[7][4][64];
    __shared__ float SpPart[8][7];
    int bhn = blockIdx.x;
    int n = bhn & 15;
    int h = (bhn >> 4) & 15;
    int b = bhn >> 8;
    int t = threadIdx.x;

    if (t < 128) {
        const float* qp = g_qpool + (size_t)(b * NCH + n) * DD + h * HD;
        const float* kr = g_qkv + ((size_t)(b * LL + n * CC + t)) * TD + DD + h * HD;
        float acc = 0.f;
#pragma unroll
        for (int d = 0; d < HD; d++) acc += qp[d] * kr[d];
        c2s[t] = acc;
    }
    __syncthreads();

    {
        int d = t & 63, quarter = t >> 6;
        const float* vbase = g_qkv
            + ((size_t)(b * LL + n * CC + quarter * 32)) * TD + 2 * DD + h * HD + d;
        const float* cp = c2s + quarter * 32;
        float M[7] = {0.f, 0.f, 0.f, 0.f, 0.f, 0.f, 0.f};
#pragma unroll 8
        for (int c = 0; c < 32; c++) {
            float v = vbase[(size_t)c * TD];
            float x = cp[c];
            float term = v;
            M[0] += term; term *= x;
            M[1] += term; term *= x;
            M[2] += term; term *= x;
            M[3] += term; term *= x;
            M[4] += term; term *= x;
            M[5] += term; term *= x;
            M[6] += term;
        }
#pragma unroll
        for (int p = 0; p < 7; p++) Mpart[p][quarter][d] = M[p];
    }

    if (t >= 128 && t < 184) {
        int u = t - 128;
        int p = u % 7, seg = u / 7;
        const float* cp = c2s + seg * 16;
        float s = 0.f;
        for (int c = 0; c < 16; c++) {
            float x = cp[c], pw = 1.f;
            for (int q = 0; q < p; q++) pw *= x;
            s += pw;
        }
        SpPart[seg][p] = s;
    }
    __syncthreads();

    if (t < 64) {
#pragma unroll
        for (int p = 0; p < 7; p++)
            g_M[(size_t)bhn * 448 + p * 64 + t] =
                (Mpart[p][0][t] + Mpart[p][1][t]) +
                (Mpart[p][2][t] + Mpart[p][3][t]);
    } else if (t < 71) {
        int p = t - 64;
        float s = 0.f;
#pragma unroll
        for (int seg = 0; seg < 8; seg++) s += SpPart[seg][p];
        g_Sp[bhn * 7 + p] = s;
    }
}

// ---------------- fused attention: Taylor off-diag, exact diag --------------
constexpr int ATTN_SMEM_FLOATS = 51504;

__global__ __launch_bounds__(256) void attn_kernel()
{
    extern __shared__ float sm[];
    float* qT    = sm;
    float* kT    = sm + 8192;
    float* S     = sm + 16384;
    float* vs    = sm + 32896;
    float* aall  = sm + 41088;
    float* Mom   = sm + 43136;
    float* Sp    = sm + 50304;
    float* Gs    = sm + 50416;
    float* csufh = sm + 51440;

    int idx = blockIdx.x;
    int nq  = (NCH - 1) - (idx >> 5);      // big chunks first
    int bh  = idx & 31;
    int b   = bh >> 4;
    int h   = bh & 15;
    int t   = threadIdx.x;

    const float* qkv_b = g_qkv + (size_t)b * LL * TD;

    for (int i = t; i < 128 * 16; i += 256) {
        int r = i >> 4, d4 = (i & 15) * 4;
        const float* rowp = qkv_b + (size_t)(nq * CC + r) * TD + h * HD + d4;
        float4 q4 = *(const float4*)(rowp);
        float4 k4 = *(const float4*)(rowp + DD);
        float4 v4 = *(const float4*)(rowp + 2 * DD);
        qT[(d4 + 0) * 128 + r] = q4.x;
        qT[(d4 + 1) * 128 + r] = q4.y;
        qT[(d4 + 2) * 128 + r] = q4.z;
        qT[(d4 + 3) * 128 + r] = q4.w;
        kT[(d4 + 0) * 128 + r] = k4.x;
        kT[(d4 + 1) * 128 + r] = k4.y;
        kT[(d4 + 2) * 128 + r] = k4.z;
        kT[(d4 + 3) * 128 + r] = k4.w;
        *(float4*)&vs[r * 64 + d4] = v4;
    }
    {
        const float* mg = g_M + (size_t)((b * HH + h) * NCH) * 448;
        for (int i = t; i < nq * 448; i += 256) Mom[i] = mg[i];
        const float* sg = g_Sp + (b * HH + h) * NCH * 7;
        for (int i = t; i < nq * 7; i += 256) Sp[i] = sg[i];
    }
    __syncthreads();

    for (int i = t; i < 16 * 64; i += 256) {
        int g = i >> 6, d = i & 63;
        const float* vp = vs + (g * 8) * 64 + d;
        float s = 0.f;
#pragma unroll
        for (int c = 0; c < 8; c++) s += vp[c * 64];
        Gs[i] = s;
    }
    if (t < 64) {
        float s = 0.f;
        for (int n = nq + 1; n < NCH; n++)
            s += g_csum[(size_t)(b * NCH + n) * DD + h * HD + t];
        csufh[t] = s;
    }

    for (int task = t; task < 128 * nq; task += 256) {
        int rr = task & 127, j = task >> 7;
        const float* kp = g_kpool + (size_t)(b * NCH + j) * DD + h * HD;
        float acc = 0.f;
#pragma unroll
        for (int d = 0; d < HD; d++) acc += qT[d * 128 + rr] * kp[d];
        aall[rr * 16 + j] = acc * INV_SCALE;
    }

    {
        int ty = t >> 4, tx = t & 15;
        float acc[8][8];
#pragma unroll
        for (int i = 0; i < 8; i++)
#pragma unroll
            for (int jx = 0; jx < 8; jx++) acc[i][jx] = 0.f;
#pragma unroll 4
        for (int d = 0; d < 64; d++) {
            float qa[8], kb[8];
            *(float4*)(qa)     = *(const float4*)&qT[d * 128 + ty * 4];
            *(float4*)(qa + 4) = *(const float4*)&qT[d * 128 + 64 + ty * 4];
            *(float4*)(kb)     = *(const float4*)&kT[d * 128 + tx * 4];
            *(float4*)(kb + 4) = *(const float4*)&kT[d * 128 + 64 + tx * 4];
#pragma unroll
            for (int i = 0; i < 8; i++)
#pragma unroll
                for (int jx = 0; jx < 8; jx++)
                    acc[i][jx] += qa[i] * kb[jx];
        }
#pragma unroll
        for (int ii = 0; ii < 2; ii++)
#pragma unroll
            for (int iy = 0; iy < 4; iy++) {
                int rr = ii * 64 + ty * 4 + iy;
#pragma unroll
                for (int jj = 0; jj < 2; jj++)
#pragma unroll
                    for (int jx = 0; jx < 4; jx++) {
                        int cc = jj * 64 + tx * 4 + jx;
                        S[rr * 129 + cc] = acc[ii * 4 + iy][jj * 4 + jx] * INV_SCALE;
                    }
            }
    }
    __syncthreads();

    if (t < 64) {
        float acc = 0.f;
#pragma unroll
        for (int g = 15; g >= 0; g--) {
            float cur = Gs[g * 64 + t];
            Gs[g * 64 + t] = acc;
            acc += cur;
        }
    }
    __syncthreads();

    int r  = t >> 1;
    int dh = (t & 1) * 32;
    int l  = nq * CC + r;

    float O[32];
    {
        int g = r >> 3;
        const float* gp = Gs + g * 64 + dh;
        const float* cp = csufh + dh;
#pragma unroll
        for (int i = 0; i < 32; i += 4) {
            float4 gv = *(const float4*)(gp + i);
            float4 cv = *(const float4*)(cp + i);
            O[i + 0] = gv.x + cv.x;
            O[i + 1] = gv.y + cv.y;
            O[i + 2] = gv.z + cv.z;
            O[i + 3] = gv.w + cv.w;
        }
        int gend = g * 8 + 8;
        for (int c = r + 1; c < gend; c++) {
            const float* vrow = vs + c * 64 + dh;
#pragma unroll
            for (int i = 0; i < 32; i += 4) {
                float4 vv = *(const float4*)(vrow + i);
                O[i + 0] += vv.x;
                O[i + 1] += vv.y;
                O[i + 2] += vv.z;
                O[i + 3] += vv.w;
            }
        }
    }
    float Z = (float)(LL - 1 - l);

    for (int j = 0; j < nq; j++) {
        float a  = aall[r * 16 + j];
        float g1 = a;
        float g2 = g1 * a * 0.5f;
        float g3 = g2 * a * (1.f / 3.f);
        float g4 = g3 * a * 0.25f;
        float g5 = g4 * a * 0.2f;
        float g6 = g5 * a * (1.f / 6.f);
        const float* sp = Sp + j * 7;
        Z += sp[0] + g1 * sp[1] + g2 * sp[2] + g3 * sp[3]
                   + g4 * sp[4] + g5 * sp[5] + g6 * sp[6];
        const float* Mj = Mom + j * 448 + dh;
#pragma unroll
        for (int i = 0; i < 32; i += 4) {
            float4 m0 = *(const float4*)(Mj + 0 * 64 + i);
            float4 m1 = *(const float4*)(Mj + 1 * 64 + i);
            float4 m2 = *(const float4*)(Mj + 2 * 64 + i);
            float4 m3 = *(const float4*)(Mj + 3 * 64 + i);
            float4 m4 = *(const float4*)(Mj + 4 * 64 + i);
            float4 m5 = *(const float4*)(Mj + 5 * 64 + i);
            float4 m6 = *(const float4*)(Mj + 6 * 64 + i);
            O[i + 0] += m0.x + g1 * m1.x + g2 * m2.x + g3 * m3.x
                             + g4 * m4.x + g5 * m5.x + g6 * m6.x;
            O[i + 1] += m0.y + g1 * m1.y + g2 * m2.y + g3 * m3.y
                             + g4 * m4.y + g5 * m5.y + g6 * m6.y;
            O[i + 2] += m0.z + g1 * m1.z + g2 * m2.z + g3 * m3.z
                             + g4 * m4.z + g5 * m5.z + g6 * m6.z;
            O[i + 3] += m0.w + g1 * m1.w + g2 * m2.w + g3 * m3.w
                             + g4 * m4.w + g5 * m5.w + g6 * m6.w;
        }
    }

    {
        const float* Srow = S + r * 129;
        for (int c = 0; c <= r; c++) {
            float w = __expf(Srow[c]);
            Z += w;
            const float* vrow = vs + c * 64 + dh;
#pragma unroll
            for (int i = 0; i < 32; i += 4) {
                float4 vv = *(const float4*)(vrow + i);
                O[i + 0] += w * vv.x;
                O[i + 1] += w * vv.y;
                O[i + 2] += w * vv.z;
                O[i + 3] += w * vv.w;
            }
        }
    }

    float inv = 1.0f / Z;
    size_t obase = ((size_t)(b * LL + l)) * DD + h * HD + dh;
#pragma unroll
    for (int i = 0; i < 32; i += 2) {
        float v0 = O[i + 0] * inv;
        float v1 = O[i + 1] * inv;
        __nv_bfloat16 h0 = __float2bfloat16(v0);
        __nv_bfloat16 h1 = __float2bfloat16(v1);
        __nv_bfloat16 l0 = __float2bfloat16(v0 - __bfloat162float(h0));
        __nv_bfloat16 l1 = __float2bfloat16(v1 - __bfloat162float(h1));
        *(__nv_bfloat162*)(g_attn_hi + obase + i) = __nv_bfloat162(h0, h1);
        *(__nv_bfloat162*)(g_attn_lo + obase + i) = __nv_bfloat162(l0, l1);
    }
}

// ---------------- launch --------------------------------------------------
extern "C" void kernel_launch(void* const* d_in, const int* in_sizes, int n_in,
                              void* d_out, int out_size)
{
    const float* x     = (const float*)d_in[0];
    const float* w_qkv = (const float*)d_in[1];
    const float* b_qkv = (const float*)d_in[2];
    const float* w_o   = (const float*)d_in[3];
    const float* b_o   = (const float*)d_in[4];
    float* out         = (float*)d_out;

    // merged input/weight split conversions (one launch)
    split_all<<<NB_RM + NB_T1 + NB_T2, 256>>>(x, w_qkv, w_o);

    // 1) QKV projection (+ fused chunk pooling)
    {
        cudaFuncSetAttribute(mma_gemm<0>, cudaFuncAttributeMaxDynamicSharedMemorySize, GSMEM);
        dim3 grid(TD / 128, ML / 128);
        mma_gemm<0><<<grid, 256, GSMEM>>>(b_qkv, nullptr);
    }
    // 2) fused c2t/moments
    c2t_moments_kernel<<<BB * HH * NCH, 256>>>();
    // 3) fused attention
    {
        const int smem_bytes = ATTN_SMEM_FLOATS * 4;
        cudaFuncSetAttribute(attn_kernel, cudaFuncAttributeMaxDynamicSharedMemorySize, smem_bytes);
        attn_kernel<<<BB * HH * NCH, 256, smem_bytes>>>();
    }
    // 4) output projection
    {
        cudaFuncSetAttribute(mma_gemm<1>, cudaFuncAttributeMaxDynamicSharedMemorySize, GSMEM);
        dim3 grid(DD / 128, ML / 128);
        mma_gemm<1><<<grid, 256, GSMEM>>>(b_o, out);
    }
}

// round 16
// speedup vs baseline: 1.5154x; 1.5154x over previous
#include <cuda_runtime.h>
#include <cuda_bf16.h>
#include <cstdint>
#include <math.h>

// Problem constants
constexpr int BB  = 2;
constexpr int LL  = 2048;
constexpr int DD  = 1024;
constexpr int TD  = 3072;   // 3*D
constexpr int HH  = 16;     // heads
constexpr int HD  = 64;     // head dim
constexpr int CC  = 128;    // chunk size
constexpr int NCH = 16;     // num chunks
constexpr float INV_SCALE = 1.0f / 32.0f;   // 1/sqrt(1024)
constexpr int ML  = BB * LL;                // 4096 rows

// ---------------- device scratch (static globals: allocation-free) ----------
__device__ float g_qkv  [(size_t)BB * LL * TD];
__device__ float g_qpool[BB * NCH * DD];
__device__ float g_kpool[BB * NCH * DD];
__device__ float g_csum [BB * NCH * DD];
__device__ float g_M    [(size_t)BB * HH * NCH * 7 * HD];  // moments M_p[d]
__device__ float g_Sp   [BB * HH * NCH * 7];               // scalar sums S_p

// split bf16 operands for tensor-core GEMMs
__device__ __nv_bfloat16 g_x_hi   [(size_t)ML * DD];
__device__ __nv_bfloat16 g_x_lo   [(size_t)ML * DD];
__device__ __nv_bfloat16 g_attn_hi[(size_t)ML * DD];
__device__ __nv_bfloat16 g_attn_lo[(size_t)ML * DD];
__device__ __nv_bfloat16 g_wqkv_hi[(size_t)TD * DD];   // transposed [N=3072][K=1024]
__device__ __nv_bfloat16 g_wqkv_lo[(size_t)TD * DD];
__device__ __nv_bfloat16 g_wo_hi  [(size_t)DD * DD];   // transposed [N=1024][K=1024]
__device__ __nv_bfloat16 g_wo_lo  [(size_t)DD * DD];

// ================= baseline-PTX helpers =====================================
__device__ __forceinline__ uint32_t smem_u32(const void* p) {
    uint32_t a;
    asm("{ .reg .u64 t; cvta.to.shared.u64 t, %1; cvt.u32.u64 %0, t; }"
        : "=r"(a) : "l"(p));
    return a;
}
__device__ __forceinline__ void cp_async16(uint32_t dst, const void* src) {
    asm volatile("cp.async.cg.shared.global [%0], [%1], 16;" :: "r"(dst), "l"(src));
}
__device__ __forceinline__ void cp_commit() {
    asm volatile("cp.async.commit_group;" ::: "memory");
}
template <int NW>
__device__ __forceinline__ void cp_wait() {
    asm volatile("cp.async.wait_group %0;" :: "n"(NW) : "memory");
}
__device__ __forceinline__ void ldm_x4(uint32_t* r, uint32_t addr) {
    asm volatile("ldmatrix.sync.aligned.m8n8.x4.shared.b16 {%0,%1,%2,%3}, [%4];"
                 : "=r"(r[0]), "=r"(r[1]), "=r"(r[2]), "=r"(r[3]) : "r"(addr));
}
__device__ __forceinline__ void mma16816(float* d, const uint32_t* a, const uint32_t* b) {
    asm volatile(
        "mma.sync.aligned.m16n8k16.row.col.f32.bf16.bf16.f32 "
        "{%0,%1,%2,%3}, {%4,%5,%6,%7}, {%8,%9}, {%0,%1,%2,%3};"
        : "+f"(d[0]), "+f"(d[1]), "+f"(d[2]), "+f"(d[3])
        : "r"(a[0]), "r"(a[1]), "r"(a[2]), "r"(a[3]), "r"(b[0]), "r"(b[1]));
}

// ================= merged split/transpose conversion kernel =================
constexpr int NB_RM = (ML * DD) / 256;
constexpr int NB_T1 = (TD / 32) * (DD / 32);
constexpr int NB_T2 = (DD / 32) * (DD / 32);

__global__ void split_all(const float* __restrict__ x,
                          const float* __restrict__ wqkv,
                          const float* __restrict__ wo)
{
    int blk = blockIdx.x;
    int t = threadIdx.x;
    if (blk < NB_RM) {
        int i = blk * 256 + t;
        float v = x[i];
        __nv_bfloat16 h = __float2bfloat16(v);
        g_x_hi[i] = h;
        g_x_lo[i] = __float2bfloat16(v - __bfloat162float(h));
        return;
    }
    blk -= NB_RM;
    const float* in;
    __nv_bfloat16 *hi, *lo;
    int Nc, bx;
    if (blk < NB_T1) {
        in = wqkv; hi = g_wqkv_hi; lo = g_wqkv_lo; Nc = TD;
        bx = blk % (TD / 32);
        blk /= (TD / 32);
    } else {
        blk -= NB_T1;
        in = wo; hi = g_wo_hi; lo = g_wo_lo; Nc = DD;
        bx = blk % (DD / 32);
        blk /= (DD / 32);
    }
    int nBase = bx * 32, kBase = blk * 32;

    __shared__ float tile[32][33];
    int tx = t & 31, ty = t >> 5;     // 32 x 8
#pragma unroll
    for (int j = 0; j < 32; j += 8)
        tile[ty + j][tx] = in[(size_t)(kBase + ty + j) * Nc + nBase + tx];
    __syncthreads();
#pragma unroll
    for (int j = 0; j < 32; j += 8) {
        float v = tile[tx][ty + j];
        size_t o = (size_t)(nBase + ty + j) * DD + kBase + tx;
        __nv_bfloat16 h = __float2bfloat16(v);
        hi[o] = h;
        lo[o] = __float2bfloat16(v - __bfloat162float(h));
    }
}

// ================= mma.sync GEMM — R14 two-sync mainloop (best measured) ====
constexpr int GP    = 40;
constexpr int GTILE = 128 * GP;
constexpr int GSTG  = 4 * GTILE;
constexpr int GSMEM = 2 * GSTG * 2;

template <int MODE>
__global__ __launch_bounds__(256, 2) void mma_gemm(const float* __restrict__ bias,
                                                   float* __restrict__ Cext)
{
    const int N = (MODE == 0) ? TD : DD;
    const int K = DD;
    const __nv_bfloat16* Ah = (MODE == 0) ? g_x_hi : g_attn_hi;
    const __nv_bfloat16* Al = (MODE == 0) ? g_x_lo : g_attn_lo;
    const __nv_bfloat16* Bh = (MODE == 0) ? g_wqkv_hi : g_wo_hi;
    const __nv_bfloat16* Bl = (MODE == 0) ? g_wqkv_lo : g_wo_lo;
    float* C = (MODE == 0) ? g_qkv : Cext;

    extern __shared__ __nv_bfloat16 smem[];
    uint32_t sb = smem_u32(smem);

    int t = threadIdx.x, lane = t & 31, wid = t >> 5;
    int wm = wid & 3, wn = wid >> 2;
    int bm = blockIdx.y * 128, bn = blockIdx.x * 128;

    const __nv_bfloat16* srcs[4] = {
        Ah + (size_t)bm * K, Al + (size_t)bm * K,
        Bh + (size_t)bn * K, Bl + (size_t)bn * K
    };

    int r0c = t >> 2, c0c = t & 3;
    int r1c = (t + 256) >> 2, c1c = (t + 256) & 3;

    auto load_stage = [&](int st, int s) {
        int ks = s * 32;
#pragma unroll
        for (int ten = 0; ten < 4; ten++) {
            const __nv_bfloat16* base = srcs[ten] + ks;
            uint32_t dst = sb + (uint32_t)(st * GSTG + ten * GTILE) * 2;
            cp_async16(dst + (uint32_t)(r0c * GP + c0c * 8) * 2,
                       base + (size_t)r0c * K + c0c * 8);
            cp_async16(dst + (uint32_t)(r1c * GP + c1c * 8) * 2,
                       base + (size_t)r1c * K + c1c * 8);
        }
    };

    float acc[2][8][4];
#pragma unroll
    for (int i = 0; i < 2; i++)
#pragma unroll
        for (int j = 0; j < 8; j++)
#pragma unroll
            for (int q = 0; q < 4; q++) acc[i][j][q] = 0.f;

    load_stage(0, 0);
    cp_commit();

    const int S = K / 32;
    for (int s = 0; s < S; s++) {
        if (s + 1 < S) { load_stage((s + 1) & 1, s + 1); cp_commit(); cp_wait<1>(); }
        else           { cp_wait<0>(); }
        __syncthreads();

        int st = s & 1;
        uint32_t baseAh = sb + (uint32_t)(st * GSTG + 0 * GTILE) * 2;
        uint32_t baseAl = sb + (uint32_t)(st * GSTG + 1 * GTILE) * 2;
        uint32_t baseBh = sb + (uint32_t)(st * GSTG + 2 * GTILE) * 2;
        uint32_t baseBl = sb + (uint32_t)(st * GSTG + 3 * GTILE) * 2;

#pragma unroll
        for (int kk = 0; kk < 2; kk++) {
            int k0 = kk * 16;
            uint32_t ah[2][4], al[2][4], bb[4][4];

            uint32_t aoff = (uint32_t)(((wm * 32 + (lane & 15)) * GP
                                        + k0 + (lane >> 4) * 8) * 2);
            ldm_x4(ah[0], baseAh + aoff);
            ldm_x4(ah[1], baseAh + aoff + 16 * GP * 2);

            uint32_t brow = (uint32_t)(wn * 64 + (lane & 7) + ((lane >> 4) << 3));
            uint32_t boff = (uint32_t)((brow * GP + k0 + ((lane >> 3) & 1) * 8) * 2);
#pragma unroll
            for (int bt = 0; bt < 4; bt++)
                ldm_x4(bb[bt], baseBh + boff + bt * 16 * GP * 2);

            // pass 1: Ah * Bh
#pragma unroll
            for (int mt = 0; mt < 2; mt++)
#pragma unroll
                for (int nt = 0; nt < 8; nt++)
                    mma16816(acc[mt][nt], ah[mt], &bb[nt >> 1][(nt & 1) * 2]);

            // pass 2: Al * Bh
            ldm_x4(al[0], baseAl + aoff);
            ldm_x4(al[1], baseAl + aoff + 16 * GP * 2);
#pragma unroll
            for (int mt = 0; mt < 2; mt++)
#pragma unroll
                for (int nt = 0; nt < 8; nt++)
                    mma16816(acc[mt][nt], al[mt], &bb[nt >> 1][(nt & 1) * 2]);

            // pass 3: Ah * Bl
#pragma unroll
            for (int bt = 0; bt < 4; bt++)
                ldm_x4(bb[bt], baseBl + boff + bt * 16 * GP * 2);
#pragma unroll
            for (int mt = 0; mt < 2; mt++)
#pragma unroll
                for (int nt = 0; nt < 8; nt++)
                    mma16816(acc[mt][nt], ah[mt], &bb[nt >> 1][(nt & 1) * 2]);
        }
        __syncthreads();
    }

    int mbase = bm + wm * 32, nbase = bn + wn * 64;
    int rr = lane >> 2, cc = (lane & 3) * 2;
#pragma unroll
    for (int mt = 0; mt < 2; mt++) {
#pragma unroll
        for (int nt = 0; nt < 8; nt++) {
            int col = nbase + nt * 8 + cc;
            float2 bv = *(const float2*)(bias + col);
            int row0 = mbase + mt * 16 + rr;
            float2 o0 = { acc[mt][nt][0] + bv.x, acc[mt][nt][1] + bv.y };
            float2 o1 = { acc[mt][nt][2] + bv.x, acc[mt][nt][3] + bv.y };
            *(float2*)(C + (size_t)row0 * N + col)       = o0;
            *(float2*)(C + (size_t)(row0 + 8) * N + col) = o1;
        }
    }

    // ---- fused chunk pooling (MODE 0): this CTA tile = chunk blockIdx.y ----
    if (MODE == 0) {
        float cs[16];
#pragma unroll
        for (int nt = 0; nt < 8; nt++) {
            cs[nt * 2 + 0] = acc[0][nt][0] + acc[0][nt][2]
                           + acc[1][nt][0] + acc[1][nt][2];
            cs[nt * 2 + 1] = acc[0][nt][1] + acc[0][nt][3]
                           + acc[1][nt][1] + acc[1][nt][3];
        }
#pragma unroll
        for (int off = 16; off >= 4; off >>= 1)
#pragma unroll
            for (int i = 0; i < 16; i++)
                cs[i] += __shfl_down_sync(0xffffffffu, cs[i], off);

        float* red = (float*)smem;
        if (lane < 4) {
#pragma unroll
            for (int nt = 0; nt < 8; nt++) {
                red[wm * 128 + wn * 64 + nt * 8 + lane * 2 + 0] = cs[nt * 2 + 0];
                red[wm * 128 + wn * 64 + nt * 8 + lane * 2 + 1] = cs[nt * 2 + 1];
            }
        }
        __syncthreads();
        if (t < 128) {
            float sum = red[0 * 128 + t] + red[1 * 128 + t]
                      + red[2 * 128 + t] + red[3 * 128 + t];
            int gcol = bn + t;
            sum += 128.0f * bias[gcol];
            int chunk = blockIdx.y;
            if (gcol < DD)
                g_qpool[chunk * DD + gcol] = sum * (1.0f / 128.0f);
            else if (gcol < 2 * DD)
                g_kpool[chunk * DD + (gcol - DD)] = sum * (1.0f / 128.0f);
            else
                g_csum[chunk * DD + (gcol - 2 * DD)] = sum;
        }
    }
}

// ---------------- fused c2t + moments: one block per (b,h,n), 256 thr -------
__global__ __launch_bounds__(256) void c2t_moments_kernel()   // grid = BB*HH*NCH
{
    __shared__ float c2s[128];
    __shared__ float Mpart[7][4][64];
    __shared__ float SpPart[8][7];
    int bhn = blockIdx.x;
    int n = bhn & 15;
    int h = (bhn >> 4) & 15;
    int b = bhn >> 8;
    int t = threadIdx.x;

    if (t < 128) {
        const float* qp = g_qpool + (size_t)(b * NCH + n) * DD + h * HD;
        const float* kr = g_qkv + ((size_t)(b * LL + n * CC + t)) * TD + DD + h * HD;
        float acc = 0.f;
#pragma unroll
        for (int d = 0; d < HD; d++) acc += qp[d] * kr[d];
        c2s[t] = acc;
    }
    __syncthreads();

    {
        int d = t & 63, quarter = t >> 6;
        const float* vbase = g_qkv
            + ((size_t)(b * LL + n * CC + quarter * 32)) * TD + 2 * DD + h * HD + d;
        const float* cp = c2s + quarter * 32;
        float M[7] = {0.f, 0.f, 0.f, 0.f, 0.f, 0.f, 0.f};
#pragma unroll 8
        for (int c = 0; c < 32; c++) {
            float v = vbase[(size_t)c * TD];
            float x = cp[c];
            float term = v;
            M[0] += term; term *= x;
            M[1] += term; term *= x;
            M[2] += term; term *= x;
            M[3] += term; term *= x;
            M[4] += term; term *= x;
            M[5] += term; term *= x;
            M[6] += term;
        }
#pragma unroll
        for (int p = 0; p < 7; p++) Mpart[p][quarter][d] = M[p];
    }

    if (t >= 128 && t < 184) {
        int u = t - 128;
        int p = u % 7, seg = u / 7;
        const float* cp = c2s + seg * 16;
        float s = 0.f;
        for (int c = 0; c < 16; c++) {
            float x = cp[c], pw = 1.f;
            for (int q = 0; q < p; q++) pw *= x;
            s += pw;
        }
        SpPart[seg][p] = s;
    }
    __syncthreads();

    if (t < 64) {
#pragma unroll
        for (int p = 0; p < 7; p++)
            g_M[(size_t)bhn * 448 + p * 64 + t] =
                (Mpart[p][0][t] + Mpart[p][1][t]) +
                (Mpart[p][2][t] + Mpart[p][3][t]);
    } else if (t < 71) {
        int p = t - 64;
        float s = 0.f;
#pragma unroll
        for (int seg = 0; seg < 8; seg++) s += SpPart[seg][p];
        g_Sp[bhn * 7 + p] = s;
    }
}

// ---------------- fused attention: Taylor off-diag, exact diag --------------
constexpr int ATTN_SMEM_FLOATS = 51504;

__global__ __launch_bounds__(256) void attn_kernel()
{
    extern __shared__ float sm[];
    float* qT    = sm;
    float* kT    = sm + 8192;
    float* S     = sm + 16384;
    float* vs    = sm + 32896;
    float* aall  = sm + 41088;
    float* Mom   = sm + 43136;
    float* Sp    = sm + 50304;
    float* Gs    = sm + 50416;
    float* csufh = sm + 51440;

    int idx = blockIdx.x;
    int nq  = (NCH - 1) - (idx >> 5);      // big chunks first
    int bh  = idx & 31;
    int b   = bh >> 4;
    int h   = bh & 15;
    int t   = threadIdx.x;

    const float* qkv_b = g_qkv + (size_t)b * LL * TD;

    for (int i = t; i < 128 * 16; i += 256) {
        int r = i >> 4, d4 = (i & 15) * 4;
        const float* rowp = qkv_b + (size_t)(nq * CC + r) * TD + h * HD + d4;
        float4 q4 = *(const float4*)(rowp);
        float4 k4 = *(const float4*)(rowp + DD);
        float4 v4 = *(const float4*)(rowp + 2 * DD);
        qT[(d4 + 0) * 128 + r] = q4.x;
        qT[(d4 + 1) * 128 + r] = q4.y;
        qT[(d4 + 2) * 128 + r] = q4.z;
        qT[(d4 + 3) * 128 + r] = q4.w;
        kT[(d4 + 0) * 128 + r] = k4.x;
        kT[(d4 + 1) * 128 + r] = k4.y;
        kT[(d4 + 2) * 128 + r] = k4.z;
        kT[(d4 + 3) * 128 + r] = k4.w;
        *(float4*)&vs[r * 64 + d4] = v4;
    }
    {
        const float* mg = g_M + (size_t)((b * HH + h) * NCH) * 448;
        for (int i = t; i < nq * 448; i += 256) Mom[i] = mg[i];
        const float* sg = g_Sp + (b * HH + h) * NCH * 7;
        for (int i = t; i < nq * 7; i += 256) Sp[i] = sg[i];
    }
    __syncthreads();

    for (int i = t; i < 16 * 64; i += 256) {
        int g = i >> 6, d = i & 63;
        const float* vp = vs + (g * 8) * 64 + d;
        float s = 0.f;
#pragma unroll
        for (int c = 0; c < 8; c++) s += vp[c * 64];
        Gs[i] = s;
    }
    if (t < 64) {
        float s = 0.f;
        for (int n = nq + 1; n < NCH; n++)
            s += g_csum[(size_t)(b * NCH + n) * DD + h * HD + t];
        csufh[t] = s;
    }

    for (int task = t; task < 128 * nq; task += 256) {
        int rr = task & 127, j = task >> 7;
        const float* kp = g_kpool + (size_t)(b * NCH + j) * DD + h * HD;
        float acc = 0.f;
#pragma unroll
        for (int d = 0; d < HD; d++) acc += qT[d * 128 + rr] * kp[d];
        aall[rr * 16 + j] = acc * INV_SCALE;
    }

    {
        int ty = t >> 4, tx = t & 15;
        float acc[8][8];
#pragma unroll
        for (int i = 0; i < 8; i++)
#pragma unroll
            for (int jx = 0; jx < 8; jx++) acc[i][jx] = 0.f;
#pragma unroll 4
        for (int d = 0; d < 64; d++) {
            float qa[8], kb[8];
            *(float4*)(qa)     = *(const float4*)&qT[d * 128 + ty * 4];
            *(float4*)(qa + 4) = *(const float4*)&qT[d * 128 + 64 + ty * 4];
            *(float4*)(kb)     = *(const float4*)&kT[d * 128 + tx * 4];
            *(float4*)(kb + 4) = *(const float4*)&kT[d * 128 + 64 + tx * 4];
#pragma unroll
            for (int i = 0; i < 8; i++)
#pragma unroll
                for (int jx = 0; jx < 8; jx++)
                    acc[i][jx] += qa[i] * kb[jx];
        }
#pragma unroll
        for (int ii = 0; ii < 2; ii++)
#pragma unroll
            for (int iy = 0; iy < 4; iy++) {
                int rr = ii * 64 + ty * 4 + iy;
#pragma unroll
                for (int jj = 0; jj < 2; jj++)
#pragma unroll
                    for (int jx = 0; jx < 4; jx++) {
                        int cc = jj * 64 + tx * 4 + jx;
                        S[rr * 129 + cc] = acc[ii * 4 + iy][jj * 4 + jx] * INV_SCALE;
                    }
            }
    }
    __syncthreads();

    if (t < 64) {
        float acc = 0.f;
#pragma unroll
        for (int g = 15; g >= 0; g--) {
            float cur = Gs[g * 64 + t];
            Gs[g * 64 + t] = acc;
            acc += cur;
        }
    }
    __syncthreads();

    int r  = t >> 1;
    int dh = (t & 1) * 32;
    int l  = nq * CC + r;

    float O[32];
    {
        int g = r >> 3;
        const float* gp = Gs + g * 64 + dh;
        const float* cp = csufh + dh;
#pragma unroll
        for (int i = 0; i < 32; i += 4) {
            float4 gv = *(const float4*)(gp + i);
            float4 cv = *(const float4*)(cp + i);
            O[i + 0] = gv.x + cv.x;
            O[i + 1] = gv.y + cv.y;
            O[i + 2] = gv.z + cv.z;
            O[i + 3] = gv.w + cv.w;
        }
        int gend = g * 8 + 8;
        for (int c = r + 1; c < gend; c++) {
            const float* vrow = vs + c * 64 + dh;
#pragma unroll
            for (int i = 0; i < 32; i += 4) {
                float4 vv = *(const float4*)(vrow + i);
                O[i + 0] += vv.x;
                O[i + 1] += vv.y;
                O[i + 2] += vv.z;
                O[i + 3] += vv.w;
            }
        }
    }
    float Z = (float)(LL - 1 - l);

    for (int j = 0; j < nq; j++) {
        float a  = aall[r * 16 + j];
        float g1 = a;
        float g2 = g1 * a * 0.5f;
        float g3 = g2 * a * (1.f / 3.f);
        float g4 = g3 * a * 0.25f;
        float g5 = g4 * a * 0.2f;
        float g6 = g5 * a * (1.f / 6.f);
        const float* sp = Sp + j * 7;
        Z += sp[0] + g1 * sp[1] + g2 * sp[2] + g3 * sp[3]
                   + g4 * sp[4] + g5 * sp[5] + g6 * sp[6];
        const float* Mj = Mom + j * 448 + dh;
#pragma unroll
        for (int i = 0; i < 32; i += 4) {
            float4 m0 = *(const float4*)(Mj + 0 * 64 + i);
            float4 m1 = *(const float4*)(Mj + 1 * 64 + i);
            float4 m2 = *(const float4*)(Mj + 2 * 64 + i);
            float4 m3 = *(const float4*)(Mj + 3 * 64 + i);
            float4 m4 = *(const float4*)(Mj + 4 * 64 + i);
            float4 m5 = *(const float4*)(Mj + 5 * 64 + i);
            float4 m6 = *(const float4*)(Mj + 6 * 64 + i);
            O[i + 0] += m0.x + g1 * m1.x + g2 * m2.x + g3 * m3.x
                             + g4 * m4.x + g5 * m5.x + g6 * m6.x;
            O[i + 1] += m0.y + g1 * m1.y + g2 * m2.y + g3 * m3.y
                             + g4 * m4.y + g5 * m5.y + g6 * m6.y;
            O[i + 2] += m0.z + g1 * m1.z + g2 * m2.z + g3 * m3.z
                             + g4 * m4.z + g5 * m5.z + g6 * m6.z;
            O[i + 3] += m0.w + g1 * m1.w + g2 * m2.w + g3 * m3.w
                             + g4 * m4.w + g5 * m5.w + g6 * m6.w;
        }
    }

    {
        const float* Srow = S + r * 129;
        for (int c = 0; c <= r; c++) {
            float w = __expf(Srow[c]);
            Z += w;
            const float* vrow = vs + c * 64 + dh;
#pragma unroll
            for (int i = 0; i < 32; i += 4) {
                float4 vv = *(const float4*)(vrow + i);
                O[i + 0] += w * vv.x;
                O[i + 1] += w * vv.y;
                O[i + 2] += w * vv.z;
                O[i + 3] += w * vv.w;
            }
        }
    }

    float inv = 1.0f / Z;
    size_t obase = ((size_t)(b * LL + l)) * DD + h * HD + dh;
#pragma unroll
    for (int i = 0; i < 32; i += 2) {
        float v0 = O[i + 0] * inv;
        float v1 = O[i + 1] * inv;
        __nv_bfloat16 h0 = __float2bfloat16(v0);
        __nv_bfloat16 h1 = __float2bfloat16(v1);
        __nv_bfloat16 l0 = __float2bfloat16(v0 - __bfloat162float(h0));
        __nv_bfloat16 l1 = __float2bfloat16(v1 - __bfloat162float(h1));
        *(__nv_bfloat162*)(g_attn_hi + obase + i) = __nv_bfloat162(h0, h1);
        *(__nv_bfloat162*)(g_attn_lo + obase + i) = __nv_bfloat162(l0, l1);
    }
}

// ---------------- launch --------------------------------------------------
extern "C" void kernel_launch(void* const* d_in, const int* in_sizes, int n_in,
                              void* d_out, int out_size)
{
    const float* x     = (const float*)d_in[0];
    const float* w_qkv = (const float*)d_in[1];
    const float* b_qkv = (const float*)d_in[2];
    const float* w_o   = (const float*)d_in[3];
    const float* b_o   = (const float*)d_in[4];
    float* out         = (float*)d_out;

    // merged input/weight split conversions (one launch)
    split_all<<<NB_RM + NB_T1 + NB_T2, 256>>>(x, w_qkv, w_o);

    // 1) QKV projection (+ fused chunk pooling)
    {
        cudaFuncSetAttribute(mma_gemm<0>, cudaFuncAttributeMaxDynamicSharedMemorySize, GSMEM);
        dim3 grid(TD / 128, ML / 128);
        mma_gemm<0><<<grid, 256, GSMEM>>>(b_qkv, nullptr);
    }
    // 2) fused c2t/moments
    c2t_moments_kernel<<<BB * HH * NCH, 256>>>();
    // 3) fused attention
    {
        const int smem_bytes = ATTN_SMEM_FLOATS * 4;
        cudaFuncSetAttribute(attn_kernel, cudaFuncAttributeMaxDynamicSharedMemorySize, smem_bytes);
        attn_kernel<<<BB * HH * NCH, 256, smem_bytes>>>();
    }
    // 4) output projection
    {
        cudaFuncSetAttribute(mma_gemm<1>, cudaFuncAttributeMaxDynamicSharedMemorySize, GSMEM);
        dim3 grid(DD / 128, ML / 128);
        mma_gemm<1><<<grid, 256, GSMEM>>>(b_o, out);
    }
}